// round 5
// baseline (speedup 1.0000x reference)
#include <cuda_runtime.h>
#include <cuda_fp16.h>
#include <cstddef>
#include <cstdint>

#define BATCH 4
#define SEQ   4096
#define DIM   1024
#define QKD   256
#define MTOT  16384

// CTA tile 256(M) x 128(N), warp tile 64x64, 8 warps, BK=64, 3 stages
#define CTM 256
#define CTN 128
#define BK  64
#define NSTAGE 3
#define PA   72                     // pitch (halfs) for A and TN-B tiles
#define PBN  136                    // pitch (halfs) for NN-B tile (BK rows x CTN)
#define ASZB (CTM*PA*2)             // 36864 B
#define BSZB (CTN*PA*2)             // 18432 B (>= BK*PBN*2 = 17408)
#define STAGEB (ASZB+BSZB)          // 55296 B
#define SMEM_DYN (NSTAGE*STAGEB)    // 165888 B

// ---------------- scratch (bss device globals; allocation-free) ----------------
__device__ __half g_hq [(size_t)MTOT*DIM];
__device__ __half g_hk [(size_t)MTOT*DIM];
__device__ __half g_hv [(size_t)MTOT*DIM];
__device__ __half g_hWq[(size_t)QKD*DIM];
__device__ __half g_hWk[(size_t)QKD*DIM];
__device__ __half g_hWv[(size_t)DIM*DIM];
__device__ __half g_qp [(size_t)MTOT*QKD];
__device__ __half g_kp [(size_t)MTOT*QKD];
__device__ __half g_vp [(size_t)MTOT*DIM];
__device__ __half g_z  [(size_t)BATCH*SEQ*SEQ];

// ---------------- helpers ----------------
__device__ __forceinline__ uint32_t s2u(const void* p) {
    return (uint32_t)__cvta_generic_to_shared(p);
}
__device__ __forceinline__ void cpa16(uint32_t dst, const void* src) {
    asm volatile("cp.async.cg.shared.global [%0], [%1], 16;" :: "r"(dst), "l"(src));
}
__device__ __forceinline__ void ldsm4(uint32_t* r, uint32_t a) {
    asm volatile("ldmatrix.sync.aligned.m8n8.x4.shared.b16 {%0,%1,%2,%3}, [%4];"
        : "=r"(r[0]), "=r"(r[1]), "=r"(r[2]), "=r"(r[3]) : "r"(a));
}
__device__ __forceinline__ void ldsm4t(uint32_t* r, uint32_t a) {
    asm volatile("ldmatrix.sync.aligned.m8n8.x4.trans.shared.b16 {%0,%1,%2,%3}, [%4];"
        : "=r"(r[0]), "=r"(r[1]), "=r"(r[2]), "=r"(r[3]) : "r"(a));
}
__device__ __forceinline__ void mma16816(float* d, const uint32_t* a, const uint32_t* b) {
    asm volatile(
        "mma.sync.aligned.m16n8k16.row.col.f32.f16.f16.f32 "
        "{%0,%1,%2,%3}, {%4,%5,%6,%7}, {%8,%9}, {%0,%1,%2,%3};"
        : "+f"(d[0]), "+f"(d[1]), "+f"(d[2]), "+f"(d[3])
        : "r"(a[0]), "r"(a[1]), "r"(a[2]), "r"(a[3]), "r"(b[0]), "r"(b[1]));
}

// ---------------- fused fp32 -> fp16 convert pre-pass ----------------
struct PPArgs {
    const float* src[6];
    __half* dst[6];
    size_t n4[6];
};
__global__ void cvt_half_k(PPArgs pp) {
    const int seg = blockIdx.y;
    const float* in = pp.src[seg];
    __half2* out = reinterpret_cast<__half2*>(pp.dst[seg]);
    const size_t n4 = pp.n4[seg];
    size_t i = (size_t)blockIdx.x * blockDim.x + threadIdx.x;
    const size_t stride = (size_t)gridDim.x * blockDim.x;
    for (; i < n4; i += stride) {
        float4 v = reinterpret_cast<const float4*>(in)[i];
        out[2 * i]     = __floats2half2_rn(v.x, v.y);
        out[2 * i + 1] = __floats2half2_rn(v.z, v.w);
    }
}

// ---------------- fp16 tensor-core GEMM ----------------
// C[m][n] = sum_k A[m][k] * B_frag(n,k)
//   BNN=false: B gmem is [N][K] (K-contig)  -> ldmatrix
//   BNN=true : B gmem is [K][N] (N-contig)  -> ldmatrix.trans
#define EPI_BIAS 0
#define EPI_SIG  1
#define EPI_NONE 2

template<int EPI, bool BNN, typename OutT>
__global__ __launch_bounds__(256, 1)
void hgemm(const __half* __restrict__ A, const __half* __restrict__ B,
           const float* __restrict__ bias, OutT* __restrict__ C,
           int K, size_t lda, size_t ldb, size_t ldc,
           size_t sA, size_t sB, size_t sC, float scale)
{
    extern __shared__ __align__(128) __half smem[];

    const int b = blockIdx.z;
    A += (size_t)b * sA;  B += (size_t)b * sB;  C += (size_t)b * sC;
    const int m0 = blockIdx.y * CTM;
    const int n0 = blockIdx.x * CTN;
    const int tid  = threadIdx.x;
    const int lane = tid & 31;
    const int warp = tid >> 5;
    const int wm = warp & 3;     // 4 warps along M (64 each)
    const int wn = warp >> 2;    // 2 warps along N (64 each)
    const uint32_t smem_base = s2u(smem);

    float acc[4][8][4];
#pragma unroll
    for (int mt = 0; mt < 4; mt++)
#pragma unroll
        for (int nt = 0; nt < 8; nt++)
#pragma unroll
            for (int i = 0; i < 4; i++) acc[mt][nt][i] = 0.f;

    const int nk = K / BK;

    auto stage = [&](int kt) {
        const uint32_t so = (uint32_t)(kt % NSTAGE) * STAGEB;
        const size_t k0 = (size_t)kt * BK;
        // A: 256 rows x 8 chunks(16B) = 2048 chunks, 8/thread
#pragma unroll
        for (int i = 0; i < 8; i++) {
            int idx = tid + i * 256;
            int r = idx >> 3, c8 = idx & 7;
            cpa16(smem_base + so + (uint32_t)(r * PA + c8 * 8) * 2,
                  A + (size_t)(m0 + r) * lda + k0 + c8 * 8);
        }
        if (!BNN) {
            // B: 128 rows x 8 chunks = 1024, 4/thread
#pragma unroll
            for (int i = 0; i < 4; i++) {
                int idx = tid + i * 256;
                int r = idx >> 3, c8 = idx & 7;
                cpa16(smem_base + so + ASZB + (uint32_t)(r * PA + c8 * 8) * 2,
                      B + (size_t)(n0 + r) * ldb + k0 + c8 * 8);
            }
        } else {
            // B: 64 k-rows x 16 chunks = 1024, 4/thread
#pragma unroll
            for (int i = 0; i < 4; i++) {
                int idx = tid + i * 256;
                int r = idx >> 4, c8 = idx & 15;
                cpa16(smem_base + so + ASZB + (uint32_t)(r * PBN + c8 * 8) * 2,
                      B + (size_t)(k0 + r) * ldb + n0 + c8 * 8);
            }
        }
    };

    // per-lane frag base offsets (bytes, relative to stage base)
    const uint32_t abase  = (uint32_t)(((wm * 64 + (lane & 15)) * PA + (lane >> 4) * 8) * 2);
    const uint32_t btbase = ASZB + (uint32_t)(((wn * 64 + (lane & 15)) * PA + (lane >> 4) * 8) * 2);
    const uint32_t bnbase = ASZB + (uint32_t)(((lane & 15) * PBN + wn * 64 + (lane >> 4) * 8) * 2);

    // prologue: 2 stages
#pragma unroll
    for (int kt = 0; kt < NSTAGE - 1; kt++) {
        stage(kt);
        asm volatile("cp.async.commit_group;");
    }

    for (int kt = 0; kt < nk; kt++) {
        asm volatile("cp.async.wait_group %0;" :: "n"(NSTAGE - 2));
        __syncthreads();

        if (kt + NSTAGE - 1 < nk) stage(kt + NSTAGE - 1);
        asm volatile("cp.async.commit_group;");

        const uint32_t so = smem_base + (uint32_t)(kt % NSTAGE) * STAGEB;
#pragma unroll
        for (int ks = 0; ks < 4; ks++) {
            uint32_t a[4][4];
#pragma unroll
            for (int mt = 0; mt < 4; mt++)
                ldsm4(a[mt], so + abase + mt * (16 * PA * 2) + ks * 32);
            uint32_t bf[8][2];
            if (!BNN) {
#pragma unroll
                for (int nt16 = 0; nt16 < 4; nt16++) {
                    uint32_t t[4];
                    ldsm4(t, so + btbase + nt16 * (16 * PA * 2) + ks * 32);
                    bf[2 * nt16][0] = t[0]; bf[2 * nt16][1] = t[2];
                    bf[2 * nt16 + 1][0] = t[1]; bf[2 * nt16 + 1][1] = t[3];
                }
            } else {
#pragma unroll
                for (int nt16 = 0; nt16 < 4; nt16++) {
                    uint32_t t[4];
                    ldsm4t(t, so + bnbase + ks * (16 * PBN * 2) + nt16 * 32);
                    bf[2 * nt16][0] = t[0]; bf[2 * nt16][1] = t[1];
                    bf[2 * nt16 + 1][0] = t[2]; bf[2 * nt16 + 1][1] = t[3];
                }
            }
#pragma unroll
            for (int mt = 0; mt < 4; mt++)
#pragma unroll
                for (int nt = 0; nt < 8; nt++)
                    mma16816(acc[mt][nt], a[mt], bf[nt]);
        }
        __syncthreads();
    }

    // ---------------- epilogue ----------------
    const int r = lane >> 2;
    const int c = lane & 3;
#pragma unroll
    for (int mt = 0; mt < 4; mt++) {
#pragma unroll
        for (int nt = 0; nt < 8; nt++) {
            float* d = acc[mt][nt];
            const int m1 = m0 + wm * 64 + mt * 16 + r;
            const int m2 = m1 + 8;
            const int nl = n0 + wn * 64 + nt * 8 + 2 * c;

            if (EPI == EPI_BIAS) {
                const float b0v = bias[nl], b1v = bias[nl + 1];
                d[0] += b0v; d[1] += b1v; d[2] += b0v; d[3] += b1v;
            } else if (EPI == EPI_SIG) {
                d[0] = 1.f / (1.f + __expf(-d[0] * scale));
                d[1] = 1.f / (1.f + __expf(-d[1] * scale));
                d[2] = 1.f / (1.f + __expf(-d[2] * scale));
                d[3] = 1.f / (1.f + __expf(-d[3] * scale));
            }

            if (sizeof(OutT) == 2) {
                __half2* Ch = reinterpret_cast<__half2*>(const_cast<OutT*>(C));
                Ch[((size_t)m1 * ldc + nl) >> 1] = __floats2half2_rn(d[0], d[1]);
                Ch[((size_t)m2 * ldc + nl) >> 1] = __floats2half2_rn(d[2], d[3]);
            } else {
                float* Cf = reinterpret_cast<float*>(const_cast<OutT*>(C));
                float2 v01; v01.x = d[0]; v01.y = d[1];
                float2 v23; v23.x = d[2]; v23.y = d[3];
                *reinterpret_cast<float2*>(&Cf[(size_t)m1 * ldc + nl]) = v01;
                *reinterpret_cast<float2*>(&Cf[(size_t)m2 * ldc + nl]) = v23;
            }
        }
    }
}

// ---------------- launcher ----------------
extern "C" void kernel_launch(void* const* d_in, const int* in_sizes, int n_in,
                              void* d_out, int out_size)
{
    (void)in_sizes; (void)n_in; (void)out_size;
    const float* q  = (const float*)d_in[0];
    const float* k  = (const float*)d_in[1];
    const float* v  = (const float*)d_in[2];
    const float* Wq = (const float*)d_in[3];
    const float* bq = (const float*)d_in[4];
    const float* Wk = (const float*)d_in[5];
    const float* bk = (const float*)d_in[6];
    const float* Wv = (const float*)d_in[7];
    const float* bv = (const float*)d_in[8];
    float* out = (float*)d_out;

    __half *hq, *hk, *hv, *hWq, *hWk, *hWv, *qp, *kp, *vp, *z;
    cudaGetSymbolAddress((void**)&hq,  g_hq);
    cudaGetSymbolAddress((void**)&hk,  g_hk);
    cudaGetSymbolAddress((void**)&hv,  g_hv);
    cudaGetSymbolAddress((void**)&hWq, g_hWq);
    cudaGetSymbolAddress((void**)&hWk, g_hWk);
    cudaGetSymbolAddress((void**)&hWv, g_hWv);
    cudaGetSymbolAddress((void**)&qp,  g_qp);
    cudaGetSymbolAddress((void**)&kp,  g_kp);
    cudaGetSymbolAddress((void**)&vp,  g_vp);
    cudaGetSymbolAddress((void**)&z,   g_z);

    cudaFuncSetAttribute(hgemm<EPI_BIAS, false, __half>, cudaFuncAttributeMaxDynamicSharedMemorySize, SMEM_DYN);
    cudaFuncSetAttribute(hgemm<EPI_SIG,  false, __half>, cudaFuncAttributeMaxDynamicSharedMemorySize, SMEM_DYN);
    cudaFuncSetAttribute(hgemm<EPI_NONE, true,  float >, cudaFuncAttributeMaxDynamicSharedMemorySize, SMEM_DYN);

    // launch 0: fused fp32->fp16 convert
    PPArgs pp;
    pp.src[0] = q;  pp.dst[0] = hq;  pp.n4[0] = (size_t)MTOT * DIM / 4;
    pp.src[1] = k;  pp.dst[1] = hk;  pp.n4[1] = (size_t)MTOT * DIM / 4;
    pp.src[2] = v;  pp.dst[2] = hv;  pp.n4[2] = (size_t)MTOT * DIM / 4;
    pp.src[3] = Wq; pp.dst[3] = hWq; pp.n4[3] = (size_t)QKD * DIM / 4;
    pp.src[4] = Wk; pp.dst[4] = hWk; pp.n4[4] = (size_t)QKD * DIM / 4;
    pp.src[5] = Wv; pp.dst[5] = hWv; pp.n4[5] = (size_t)DIM * DIM / 4;
    cvt_half_k<<<dim3(512, 6), 256>>>(pp);

    const dim3 blk(256);

    // launch 1: qp = q @ Wq^T + bq   [16384,256] fp16
    hgemm<EPI_BIAS, false, __half><<<dim3(QKD / CTN, MTOT / CTM, 1), blk, SMEM_DYN>>>(
        hq, hWq, bq, qp, DIM, DIM, DIM, QKD, 0, 0, 0, 0.f);
    // launch 2: kp
    hgemm<EPI_BIAS, false, __half><<<dim3(QKD / CTN, MTOT / CTM, 1), blk, SMEM_DYN>>>(
        hk, hWk, bk, kp, DIM, DIM, DIM, QKD, 0, 0, 0, 0.f);
    // launch 3: vp = v @ Wv^T + bv   [16384,1024] fp16
    hgemm<EPI_BIAS, false, __half><<<dim3(DIM / CTN, MTOT / CTM, 1), blk, SMEM_DYN>>>(
        hv, hWv, bv, vp, DIM, DIM, DIM, DIM, 0, 0, 0, 0.f);
    // launch 4: z = sigmoid(qp @ kp^T / 16)  per batch [4096,4096] fp16
    hgemm<EPI_SIG, false, __half><<<dim3(SEQ / CTN, SEQ / CTM, BATCH), blk, SMEM_DYN>>>(
        qp, kp, nullptr, z, QKD, QKD, QKD, SEQ,
        (size_t)SEQ * QKD, (size_t)SEQ * QKD, (size_t)SEQ * SEQ, 1.f / 16.f);
    // launch 5: out = z @ vp  per batch [4096,1024] fp32 (NN: vp is [k][n])
    hgemm<EPI_NONE, true, float><<<dim3(DIM / CTN, SEQ / CTM, BATCH), blk, SMEM_DYN>>>(
        z, vp, nullptr, out, SEQ, SEQ, DIM, DIM,
        (size_t)SEQ * SEQ, (size_t)SEQ * DIM, (size_t)SEQ * DIM, 0.f);
}